// round 3
// baseline (speedup 1.0000x reference)
#include <cuda_runtime.h>

// MoE gating: x:[4,4096,1024] f32, gate_w:[64,1024] f32.
// out (f32): top_scores [T,2] | top_idx [T,2] | total_loss [1]. T=16384.

#define H      1024
#define NE     64
#define KC     16
#define NCHUNK (H / KC)      // 64
#define TM     128
#define NT     128
#define STR    130
#define BUF    2080          // KC * STR
#define SP_STR 65
#define NBLK   128

__device__ float    g_pexp[NBLK * NE];
__device__ float    g_pz2[NBLK];
__device__ unsigned g_cnt = 0;

__device__ __forceinline__ void fma_f32x2(unsigned long long& d,
                                          unsigned long long a,
                                          unsigned long long b) {
    asm("fma.rn.f32x2 %0, %1, %2, %0;" : "+l"(d) : "l"(a), "l"(b));
}

__global__ __launch_bounds__(NT) void moe_gate(const float* __restrict__ x,
                                               const float* __restrict__ w,
                                               float* __restrict__ out,
                                               int T) {
    __shared__ __align__(16) float smem[8456];
    // xs buf0 @0, xs buf1 @2080, ws buf0 @4160, ws buf1 @6240
    // epilogue reuse: sP @0 (128*65=8320), sInv @8320, sRed @8448(4)
    __shared__ unsigned s_last;

    const int tid  = threadIdx.x;
    const int tBlk = blockIdx.x * TM;

    // compute mapping: 8 tokens (4 f32x2 pairs) x 8 experts per thread
    const int tx = tid & 7;          // experts {tx + 8j}
    const int ty = tid >> 3;         // tokens t0..t0+7
    const int t0 = ty * 8;

    unsigned long long acc[4][8];
#pragma unroll
    for (int i = 0; i < 4; i++)
#pragma unroll
        for (int j = 0; j < 8; j++) acc[i][j] = 0ull;

    // global-load mapping: x -> one token per thread (16 k floats)
    const float* xg = x + (size_t)(tBlk + tid) * H;
    // w -> half-row per thread
    const int wE = tid >> 1;
    const int wK = (tid & 1) * 8;
    const float* wg = w + (size_t)wE * H + wK;

    float4 xv[4], wv[2];
#pragma unroll
    for (int q = 0; q < 4; q++) xv[q] = *(const float4*)(xg + 4 * q);
#pragma unroll
    for (int q = 0; q < 2; q++) wv[q] = *(const float4*)(wg + 4 * q);

    // store chunk 0 into buf 0
    {
        float* xs = smem;
        float* ws = smem + 4160;
#pragma unroll
        for (int q = 0; q < 4; q++) {
            xs[(4 * q + 0) * STR + tid] = xv[q].x;
            xs[(4 * q + 1) * STR + tid] = xv[q].y;
            xs[(4 * q + 2) * STR + tid] = xv[q].z;
            xs[(4 * q + 3) * STR + tid] = xv[q].w;
        }
#pragma unroll
        for (int q = 0; q < 2; q++) {
            int k = wK + 4 * q;
            ws[(k + 0) * STR + 2 * wE]     = wv[q].x;
            ws[(k + 0) * STR + 2 * wE + 1] = wv[q].x;
            ws[(k + 1) * STR + 2 * wE]     = wv[q].y;
            ws[(k + 1) * STR + 2 * wE + 1] = wv[q].y;
            ws[(k + 2) * STR + 2 * wE]     = wv[q].z;
            ws[(k + 2) * STR + 2 * wE + 1] = wv[q].z;
            ws[(k + 3) * STR + 2 * wE]     = wv[q].w;
            ws[(k + 3) * STR + 2 * wE + 1] = wv[q].w;
        }
    }

    for (int c = 0; c < NCHUNK; c++) {
        __syncthreads();
        if (c < NCHUNK - 1) {
            const float* xp = xg + (c + 1) * KC;
            const float* wp = wg + (c + 1) * KC;
#pragma unroll
            for (int q = 0; q < 4; q++) xv[q] = *(const float4*)(xp + 4 * q);
#pragma unroll
            for (int q = 0; q < 2; q++) wv[q] = *(const float4*)(wp + 4 * q);
        }
        const float* xs = smem + (c & 1) * BUF;
        const float* ws = smem + 4160 + (c & 1) * BUF;
#pragma unroll
        for (int k = 0; k < KC; k++) {
            const float* xr = xs + k * STR + t0;
            const float* wr = ws + k * STR + 2 * tx;
            unsigned long long a[4], b[8];
#pragma unroll
            for (int i = 0; i < 4; i++)
                a[i] = *(const unsigned long long*)(xr + 2 * i);
#pragma unroll
            for (int j = 0; j < 8; j++)
                b[j] = *(const unsigned long long*)(wr + 16 * j);
#pragma unroll
            for (int i = 0; i < 4; i++)
#pragma unroll
                for (int j = 0; j < 8; j++)
                    fma_f32x2(acc[i][j], a[i], b[j]);
        }
        if (c < NCHUNK - 1) {
            float* xs2 = smem + ((c + 1) & 1) * BUF;
            float* ws2 = smem + 4160 + ((c + 1) & 1) * BUF;
#pragma unroll
            for (int q = 0; q < 4; q++) {
                xs2[(4 * q + 0) * STR + tid] = xv[q].x;
                xs2[(4 * q + 1) * STR + tid] = xv[q].y;
                xs2[(4 * q + 2) * STR + tid] = xv[q].z;
                xs2[(4 * q + 3) * STR + tid] = xv[q].w;
            }
#pragma unroll
            for (int q = 0; q < 2; q++) {
                int k = wK + 4 * q;
                ws2[(k + 0) * STR + 2 * wE]     = wv[q].x;
                ws2[(k + 0) * STR + 2 * wE + 1] = wv[q].x;
                ws2[(k + 1) * STR + 2 * wE]     = wv[q].y;
                ws2[(k + 1) * STR + 2 * wE + 1] = wv[q].y;
                ws2[(k + 2) * STR + 2 * wE]     = wv[q].z;
                ws2[(k + 2) * STR + 2 * wE + 1] = wv[q].z;
                ws2[(k + 3) * STR + 2 * wE]     = wv[q].w;
                ws2[(k + 3) * STR + 2 * wE + 1] = wv[q].w;
            }
        }
    }
    __syncthreads();

    // ---- epilogue: logits -> smem [TM][SP_STR] ----
    float* sP   = smem;
    float* sInv = smem + TM * SP_STR;
    float* sRed = sInv + TM;

#pragma unroll
    for (int i = 0; i < 4; i++)
#pragma unroll
        for (int j = 0; j < 8; j++) {
            float2 f = *(float2*)&acc[i][j];
            int e = tx + 8 * j;
            sP[(t0 + 2 * i)     * SP_STR + e] = f.x;
            sP[(t0 + 2 * i + 1) * SP_STR + e] = f.y;
        }
    __syncthreads();

    float zsq;
    {
        float* row = sP + tid * SP_STR;
        float m = row[0];
#pragma unroll 8
        for (int e = 1; e < NE; e++) m = fmaxf(m, row[e]);
        float sum = 0.0f;
        float b1 = -1e30f, b2 = -1e30f;
        int i1 = 0, i2 = 0;
        for (int e = 0; e < NE; e++) {
            float l  = row[e];
            float ex = __expf(l - m);
            sum += ex;
            row[e] = ex;
            if (l > b1)      { b2 = b1; i2 = i1; b1 = l; i1 = e; }
            else if (l > b2) { b2 = l;  i2 = e; }
        }
        float inv = 1.0f / sum;
        sInv[tid] = inv;
        float z = m + __logf(sum);
        zsq = z * z;
        float p1 = __expf(b1 - m) * inv;
        float p2 = __expf(b2 - m) * inv;
        float d  = __expf(p2 - p1);
        float q1 = 1.0f / (1.0f + d);
        float q2 = d / (1.0f + d);
        int gt = tBlk + tid;
        out[2 * gt]             = q1;
        out[2 * gt + 1]         = q2;
        out[2 * T + 2 * gt]     = (float)i1;
        out[2 * T + 2 * gt + 1] = (float)i2;
    }
#pragma unroll
    for (int off = 16; off > 0; off >>= 1)
        zsq += __shfl_down_sync(0xffffffffu, zsq, off);
    if ((tid & 31) == 0) sRed[tid >> 5] = zsq;
    __syncthreads();
    if (tid == 0)
        g_pz2[blockIdx.x] = sRed[0] + sRed[1] + sRed[2] + sRed[3];
    if (tid < NE) {
        float s = 0.0f;
#pragma unroll 4
        for (int t = 0; t < TM; t++)
            s += sP[t * SP_STR + tid] * sInv[t];
        g_pexp[blockIdx.x * NE + tid] = s;
    }

    // ---- fused finalize: last block reduces the loss ----
    __threadfence();
    __syncthreads();
    if (tid == 0)
        s_last = (atomicAdd(&g_cnt, 1u) == (unsigned)(gridDim.x - 1)) ? 1u : 0u;
    __syncthreads();
    if (s_last) {
        __threadfence();  // acquire: make other blocks' partials visible
        const int e    = tid & 63;
        const int half = tid >> 6;
        float s = 0.0f;
#pragma unroll 4
        for (int b = half; b < NBLK; b += 2) s += g_pexp[b * NE + e];
        float z2 = g_pz2[tid];
        __syncthreads();           // sP no longer needed
        float* redA = smem;        // [2][64]
        float* redZ = smem + 128;  // [128]
        redA[half * 64 + e] = s;
        redZ[tid] = z2;
        __syncthreads();
        if (tid < 64) {
            float load = (redA[tid] + redA[64 + tid]) / (float)T;
            float d  = load - 1.0f / 64.0f;
            float lb = d * d;
            float zz = redZ[tid] + redZ[tid + 64];
#pragma unroll
            for (int off = 16; off > 0; off >>= 1) {
                lb += __shfl_down_sync(0xffffffffu, lb, off);
                zz += __shfl_down_sync(0xffffffffu, zz, off);
            }
            if (tid == 0)  redA[0] = lb;
            if (tid == 32) redA[1] = lb;
            if (tid == 0)  redZ[0] = zz;
            if (tid == 32) redZ[1] = zz;
        }
        __syncthreads();
        if (tid == 0) {
            out[4 * T] = 0.01f * 64.0f * (redA[0] + redA[1])
                       + 1e-4f * ((redZ[0] + redZ[1]) / (float)T);
            g_cnt = 0;  // self-reset for next graph replay
        }
    }
}

extern "C" void kernel_launch(void* const* d_in, const int* in_sizes, int n_in,
                              void* d_out, int out_size) {
    const float* x = (const float*)d_in[0];
    const float* w = (const float*)d_in[1];
    float* out = (float*)d_out;
    int T = in_sizes[0] / H;   // 16384
    moe_gate<<<T / TM, NT>>>(x, w, out, T);
}